// round 14
// baseline (speedup 1.0000x reference)
#include <cuda_runtime.h>
#include <cstdint>

// MessagePassing: out[row[e]] += x[col[e]]  for e in [0, E)
// x: [N, 32] f32; edge_index: [2, E] int32. row = ei[0:E], col = ei[E:2E].
//
// Converged design (13 rounds): edge-parallel, 8 lanes per edge x 16B
// chunks, NC LDG.128 gather + red.global.add.v4.f32 scatter, no hot-path
// branches; scatter at ~94% of the ~6300 B/cyc B300 LTS chip cap.
// Rejected with measurements: U=8/prefetch (occupancy loss), CSR rebuild
// (build sectors ~= savings), SMEM binning (ATOMS 10x worse than LTS
// atomic ALUs), PDL + two fused zero+scatter variants (dependency
// overhead > gain). This round: final knob — 512-thread blocks (halves
// CTA count -> less wave-transition overhead; regs=30 keeps 48 warps/SM).

#define D 32
#define U 4
#define TPB 512

__device__ __forceinline__ void red_add_v4(float* dst, float4 v) {
    asm volatile("red.global.add.v4.f32 [%0], {%1, %2, %3, %4};"
                 :: "l"(dst), "f"(v.x), "f"(v.y), "f"(v.z), "f"(v.w)
                 : "memory");
}

// Handles full groups only: edges [0, ngroups*U). No branches in hot path.
__global__ __launch_bounds__(TPB) void mp_scatter_kernel(
        const float* __restrict__ x,
        const int* __restrict__ ei,
        float* __restrict__ out,
        int E, int ngroups) {
    int t = blockIdx.x * TPB + threadIdx.x;
    int g = t >> 3;                 // edge-group id: edges [g*U, g*U+U)
    if (g >= ngroups) return;
    int chunk = (t & 7) << 2;       // float offset within the 32-float row
    int e0 = g * U;

    int4 rows = __ldg(reinterpret_cast<const int4*>(ei + e0));
    int4 cols = __ldg(reinterpret_cast<const int4*>(ei + E + e0));

    int r[U] = {rows.x, rows.y, rows.z, rows.w};
    int c[U] = {cols.x, cols.y, cols.z, cols.w};

    float4 v[U];
    #pragma unroll
    for (int i = 0; i < U; i++)
        v[i] = __ldg(reinterpret_cast<const float4*>(
                   x + (long long)c[i] * D + chunk));

    #pragma unroll
    for (int i = 0; i < U; i++)
        red_add_v4(out + (long long)r[i] * D + chunk, v[i]);
}

// Scalar tail for E % U != 0 (not hit for E = 1.6M; kept for generality).
__global__ void mp_tail_kernel(const float* __restrict__ x,
                               const int* __restrict__ ei,
                               float* __restrict__ out,
                               int Estart, int E) {
    int t = blockIdx.x * blockDim.x + threadIdx.x;
    int e = Estart + (t >> 3);
    if (e >= E) return;
    int chunk = (t & 7) << 2;
    int r = ei[e];
    int c = ei[E + e];
    float4 v = __ldg(reinterpret_cast<const float4*>(
                   x + (long long)c * D + chunk));
    red_add_v4(out + (long long)r * D + chunk, v);
}

extern "C" void kernel_launch(void* const* d_in, const int* in_sizes, int n_in,
                              void* d_out, int out_size) {
    const float* x = (const float*)d_in[0];
    const int* ei = (const int*)d_in[1];
    float* out = (float*)d_out;

    const int E = in_sizes[1] / 2;    // edge_index has 2*E elements

    // 1) zero the output (harness poisons it with 0xAA)
    cudaMemsetAsync(out, 0, (size_t)out_size * sizeof(float), 0);

    // 2) gather + vectorized scatter-add, U edges per 8-lane group
    {
        int ngroups = E / U;
        long long total = (long long)ngroups * 8;
        int blocks = (int)((total + TPB - 1) / TPB);
        mp_scatter_kernel<<<blocks, TPB>>>(x, ei, out, E, ngroups);

        int tail = E - ngroups * U;
        if (tail > 0)
            mp_tail_kernel<<<(tail * 8 + 255) / 256, 256>>>(x, ei, out,
                                                            ngroups * U, E);
    }
}

// round 15
// speedup vs baseline: 1.0008x; 1.0008x over previous
#include <cuda_runtime.h>
#include <cstdint>

// MessagePassing: out[row[e]] += x[col[e]]  for e in [0, E)
// x: [N, 32] f32; edge_index: [2, E] int32. row = ei[0:E], col = ei[E:2E].
//
// FINAL (14 rounds): edge-parallel, 8 lanes per edge x 16B chunks,
// NC LDG.128 gather + red.global.add.v4.f32 scatter, no hot-path branches,
// 256-thread blocks. Scatter = ~423MB LTS traffic in ~38us = ~94% of the
// HW-measured ~6300 B/cyc B300 LTS chip cap (path-independent).
// Exhausted with measurements: U=8 / software prefetch (occupancy loss),
// 512-thread blocks (neutral), CSR rebuild (build sectors ~= savings),
// SMEM binning (ATOMS ~10x worse than the 192 LTS atomic ALUs), PDL and
// two fused zero+scatter variants (device-side dependency overhead > the
// ~3us launch-gap it could recover).

#define D 32
#define U 4

__device__ __forceinline__ void red_add_v4(float* dst, float4 v) {
    asm volatile("red.global.add.v4.f32 [%0], {%1, %2, %3, %4};"
                 :: "l"(dst), "f"(v.x), "f"(v.y), "f"(v.z), "f"(v.w)
                 : "memory");
}

// Handles full groups only: edges [0, ngroups*U). No branches in hot path.
__global__ __launch_bounds__(256) void mp_scatter_kernel(
        const float* __restrict__ x,
        const int* __restrict__ ei,
        float* __restrict__ out,
        int E, int ngroups) {
    int t = blockIdx.x * blockDim.x + threadIdx.x;
    int g = t >> 3;                 // edge-group id: edges [g*U, g*U+U)
    if (g >= ngroups) return;
    int chunk = (t & 7) << 2;       // float offset within the 32-float row
    int e0 = g * U;

    int4 rows = __ldg(reinterpret_cast<const int4*>(ei + e0));
    int4 cols = __ldg(reinterpret_cast<const int4*>(ei + E + e0));

    int r[U] = {rows.x, rows.y, rows.z, rows.w};
    int c[U] = {cols.x, cols.y, cols.z, cols.w};

    float4 v[U];
    #pragma unroll
    for (int i = 0; i < U; i++)
        v[i] = __ldg(reinterpret_cast<const float4*>(
                   x + (long long)c[i] * D + chunk));

    #pragma unroll
    for (int i = 0; i < U; i++)
        red_add_v4(out + (long long)r[i] * D + chunk, v[i]);
}

// Scalar tail for E % U != 0 (not hit for E = 1.6M; kept for generality).
__global__ void mp_tail_kernel(const float* __restrict__ x,
                               const int* __restrict__ ei,
                               float* __restrict__ out,
                               int Estart, int E) {
    int t = blockIdx.x * blockDim.x + threadIdx.x;
    int e = Estart + (t >> 3);
    if (e >= E) return;
    int chunk = (t & 7) << 2;
    int r = ei[e];
    int c = ei[E + e];
    float4 v = __ldg(reinterpret_cast<const float4*>(
                   x + (long long)c * D + chunk));
    red_add_v4(out + (long long)r * D + chunk, v);
}

extern "C" void kernel_launch(void* const* d_in, const int* in_sizes, int n_in,
                              void* d_out, int out_size) {
    const float* x = (const float*)d_in[0];
    const int* ei = (const int*)d_in[1];
    float* out = (float*)d_out;

    const int E = in_sizes[1] / 2;    // edge_index has 2*E elements

    // 1) zero the output (harness poisons it with 0xAA)
    cudaMemsetAsync(out, 0, (size_t)out_size * sizeof(float), 0);

    // 2) gather + vectorized scatter-add, U edges per 8-lane group
    {
        int ngroups = E / U;
        long long total = (long long)ngroups * 8;
        int threads = 256;
        int blocks = (int)((total + threads - 1) / threads);
        mp_scatter_kernel<<<blocks, threads>>>(x, ei, out, E, ngroups);

        int tail = E - ngroups * U;
        if (tail > 0)
            mp_tail_kernel<<<(tail * 8 + 255) / 256, 256>>>(x, ei, out,
                                                            ngroups * U, E);
    }
}

// round 17
// speedup vs baseline: 1.0069x; 1.0062x over previous
#include <cuda_runtime.h>
#include <cstdint>

// MessagePassing: out[row[e]] += x[col[e]]  for e in [0, E)
// x: [N, 32] f32; edge_index: [2, E] int32. row = ei[0:E], col = ei[E:2E].
//
// Converged scatter (R1-R15) + L2 eviction-priority hints, v2:
// sm_103 ptxas rejects inline .L2::evict_* on 128-bit loads, so use the
// createpolicy + ld.global.nc.L2::cache_hint form instead.
//   - index loads: evict_first policy (single-use stream, never displaces
//     the x/out working set)
//   - gather loads: evict_last policy (pin the 12.8MB x array in L2)
// R15 profile: ~38MB DRAM traffic vs 12.8MB compulsory edge stream ->
// ~25MB of x/out refill to eliminate.

#define D 32
#define U 4

__device__ __forceinline__ void red_add_v4(float* dst, float4 v) {
    asm volatile("red.global.add.v4.f32 [%0], {%1, %2, %3, %4};"
                 :: "l"(dst), "f"(v.x), "f"(v.y), "f"(v.z), "f"(v.w)
                 : "memory");
}

__device__ __forceinline__ int4 ldg_hint_int4(const int* p, uint64_t pol) {
    int4 r;
    asm volatile("ld.global.nc.L2::cache_hint.v4.s32 {%0, %1, %2, %3}, [%4], %5;"
                 : "=r"(r.x), "=r"(r.y), "=r"(r.z), "=r"(r.w)
                 : "l"(p), "l"(pol));
    return r;
}

__device__ __forceinline__ float4 ldg_hint_float4(const float* p, uint64_t pol) {
    float4 r;
    asm volatile("ld.global.nc.L2::cache_hint.v4.f32 {%0, %1, %2, %3}, [%4], %5;"
                 : "=f"(r.x), "=f"(r.y), "=f"(r.z), "=f"(r.w)
                 : "l"(p), "l"(pol));
    return r;
}

// Handles full groups only: edges [0, ngroups*U). No branches in hot path.
__global__ __launch_bounds__(256) void mp_scatter_kernel(
        const float* __restrict__ x,
        const int* __restrict__ ei,
        float* __restrict__ out,
        int E, int ngroups) {
    int t = blockIdx.x * blockDim.x + threadIdx.x;
    int g = t >> 3;                 // edge-group id: edges [g*U, g*U+U)
    if (g >= ngroups) return;
    int chunk = (t & 7) << 2;       // float offset within the 32-float row
    int e0 = g * U;

    uint64_t pol_stream, pol_pin;
    asm volatile("createpolicy.fractional.L2::evict_first.b64 %0, 1.0;"
                 : "=l"(pol_stream));
    asm volatile("createpolicy.fractional.L2::evict_last.b64 %0, 1.0;"
                 : "=l"(pol_pin));

    int4 rows = ldg_hint_int4(ei + e0, pol_stream);
    int4 cols = ldg_hint_int4(ei + E + e0, pol_stream);

    int r[U] = {rows.x, rows.y, rows.z, rows.w};
    int c[U] = {cols.x, cols.y, cols.z, cols.w};

    float4 v[U];
    #pragma unroll
    for (int i = 0; i < U; i++)
        v[i] = ldg_hint_float4(x + (long long)c[i] * D + chunk, pol_pin);

    #pragma unroll
    for (int i = 0; i < U; i++)
        red_add_v4(out + (long long)r[i] * D + chunk, v[i]);
}

// Scalar tail for E % U != 0 (not hit for E = 1.6M; kept for generality).
__global__ void mp_tail_kernel(const float* __restrict__ x,
                               const int* __restrict__ ei,
                               float* __restrict__ out,
                               int Estart, int E) {
    int t = blockIdx.x * blockDim.x + threadIdx.x;
    int e = Estart + (t >> 3);
    if (e >= E) return;
    int chunk = (t & 7) << 2;
    int r = ei[e];
    int c = ei[E + e];
    float4 v = __ldg(reinterpret_cast<const float4*>(
                   x + (long long)c * D + chunk));
    red_add_v4(out + (long long)r * D + chunk, v);
}

extern "C" void kernel_launch(void* const* d_in, const int* in_sizes, int n_in,
                              void* d_out, int out_size) {
    const float* x = (const float*)d_in[0];
    const int* ei = (const int*)d_in[1];
    float* out = (float*)d_out;

    const int E = in_sizes[1] / 2;    // edge_index has 2*E elements

    // 1) zero the output (harness poisons it with 0xAA)
    cudaMemsetAsync(out, 0, (size_t)out_size * sizeof(float), 0);

    // 2) gather + vectorized scatter-add, U edges per 8-lane group
    {
        int ngroups = E / U;
        long long total = (long long)ngroups * 8;
        int threads = 256;
        int blocks = (int)((total + threads - 1) / threads);
        mp_scatter_kernel<<<blocks, threads>>>(x, ei, out, E, ngroups);

        int tail = E - ngroups * U;
        if (tail > 0)
            mp_tail_kernel<<<(tail * 8 + 255) / 256, 256>>>(x, ei, out,
                                                            ngroups * U, E);
    }
}